// round 16
// baseline (speedup 1.0000x reference)
#include <cuda_runtime.h>
#include <cuda_fp16.h>
#include <math.h>

#define BATCH 2
#define SEQ   4096
#define DMODEL 1024
#define BAND  2048   // decay band: gamma^2048 = e^-10.2; tail ~1.7e-4 in quadrature

// Scratch (alloc-free rule: __device__ globals; zero-initialized at load)
__device__ __half g_Xh[BATCH * SEQ * DMODEL];
__device__ __half g_Wh[3][DMODEL * DMODEL];
__device__ __half g_QKV[3][BATCH * SEQ * DMODEL];    // Q, K, V (fp16, post-act)
__device__ __half g_Ah[(size_t)BATCH * SEQ * SEQ];   // 67 MB; out-of-band never read
__device__ float  g_decay[SEQ];
__device__ float2 g_rope[SEQ * 32];

// ---------------------------------------------------------------------------
__global__ void init_tables_kernel() {
    int i = blockIdx.x * blockDim.x + threadIdx.x;   // t*32 + cp
    if (i < SEQ * 32) {
        int t = i >> 5, cp = i & 31;
        double fr = (double)t * exp((double)cp * -0.28782313662425574);
        g_rope[i] = make_float2((float)cos(fr), (float)sin(fr));
        if (cp == 0) g_decay[t] = (float)exp((double)t * log(255.0 / 256.0));
    }
}
__global__ void cvt_kernel(const float* __restrict__ in, __half* __restrict__ out, int n) {
    int i = blockIdx.x * blockDim.x + threadIdx.x;
    if (i < n) out[i] = __float2half(in[i]);
}
// all three weights in one launch: i in [0, 3*nw)
__global__ void cvt_w_kernel(const float* __restrict__ w0, const float* __restrict__ w1,
                             const float* __restrict__ w2, __half* __restrict__ out) {
    int i = blockIdx.x * blockDim.x + threadIdx.x;
    int nw = DMODEL * DMODEL;
    if (i < 3 * nw) {
        int s = i / nw, j = i - s * nw;
        const float* w = (s == 0) ? w0 : (s == 1) ? w1 : w2;
        out[i] = __float2half(w[j]);
    }
}

__device__ __forceinline__ unsigned smem_u32(const void* p) {
    return (unsigned)__cvta_generic_to_shared(p);
}
#define CP16(dst, src) \
    asm volatile("cp.async.cg.shared.global [%0], [%1], 16;" :: "r"(dst), "l"(src))
#define CP_COMMIT()  asm volatile("cp.async.commit_group;")
#define CP_WAIT1()   asm volatile("cp.async.wait_group 1;")

#define LDSM4(R0, R1, R2, R3, ADDR) \
    asm volatile("ldmatrix.sync.aligned.m8n8.x4.shared.b16 {%0,%1,%2,%3}, [%4];" \
                 : "=r"(R0), "=r"(R1), "=r"(R2), "=r"(R3) : "r"(ADDR))
#define LDSM4T(R0, R1, R2, R3, ADDR) \
    asm volatile("ldmatrix.sync.aligned.m8n8.x4.trans.shared.b16 {%0,%1,%2,%3}, [%4];" \
                 : "=r"(R0), "=r"(R1), "=r"(R2), "=r"(R3) : "r"(ADDR))

__device__ __forceinline__ void mma16(float* c, const unsigned* a, const unsigned* b) {
    asm volatile(
        "mma.sync.aligned.m16n8k16.row.col.f32.f16.f16.f32 "
        "{%0,%1,%2,%3}, {%4,%5,%6,%7}, {%8,%9}, {%0,%1,%2,%3};"
        : "+f"(c[0]), "+f"(c[1]), "+f"(c[2]), "+f"(c[3])
        : "r"(a[0]), "r"(a[1]), "r"(a[2]), "r"(a[3]), "r"(b[0]), "r"(b[1]));
}
__device__ __forceinline__ float silu(float x) { return x / (1.0f + expf(-x)); }

// ---------------------------------------------------------------------------
// fp16 tensor-core GEMM, cp.async + ldmatrix + XOR swizzle.
// Block 64x128, K-tile 64, 256 threads, 8 warps (2x4), warp tile 32x32.
// acc = 32 regs/thread -> 3 CTAs/SM (24 warps) for latency hiding.
// 3 smem stages x 24KB, cp.async depth-2 prefetch via wait_group 1.
//
// Smem per 24KB stage: A tile [row 0..63][128B of k], chunk c at
// phys = c ^ (row&7).  B at +8192:
//   BMODE==1 (TRB, NxK): [n-row 0..127][128B of k], same swizzle.
//   BMODE==0 (NN, KxN): 2 subtiles [nh][krow 0..63][128B of n], ldmatrix.trans.
// OMODE: 1 fp16 out + anti-causal decay; banded tile skip
//          (tile computed iff col0+127 >= row0 && col0 <= row0+63+BAND)
//        2 fp16 out + rope + silu (Q/K/V projection; rope iff blockIdx.z < 2)
//        4 fp32 out + fused GroupNorm (AV epilogue; group == warp n-extent)
// TRIL:  A operand banded upper-triangular -> K loop runs
//        [row0/64, (row0+64+BAND)/64) — exactly the written A columns.
// ---------------------------------------------------------------------------
template<int BMODE, int OMODE, bool TRIL>
__global__ void __launch_bounds__(256, 3) hgemm(
    const __half* __restrict__ Ag, const __half* __restrict__ Bg,
    void* __restrict__ Cv,
    const float* __restrict__ gwp, const float* __restrict__ gbp,
    int Kdim, int lda, int ldb, int ldc,
    size_t sA, size_t sB, size_t sC)
{
    extern __shared__ __half S[];

    const int row0 = blockIdx.y * 64;
    const int col0 = blockIdx.x * 128;
    if (OMODE == 1 && (col0 + 127 < row0 || col0 > row0 + 63 + BAND)) return;

    const __half* Aop = Ag + (size_t)blockIdx.z * sA;
    const __half* Bop = Bg + (size_t)blockIdx.z * sB;

    const int tid  = threadIdx.x;
    const int lane = tid & 31;
    const int wid  = tid >> 5;
    const int wmh  = wid & 1;           // warp m-half -> m off 32
    const int wnh  = wid >> 1;          // warp n-quarter -> n off 32
    const int g    = lane >> 2;
    const int q    = lane & 3;
    const int rl   = lane & 7;
    const int hk   = (lane >> 3) & 1;
    const int hn   = (lane >> 4) & 1;

    const unsigned sbase = smem_u32(S);

    // ---- cp.async staging indices ----
    const int rowA = tid >> 2;          // 0..63   (A: 2 chunks/thread)
    const int cbA  = (tid & 3) * 2;     // chunk base 0/2/4/6
    const int ar7  = rowA & 7;
    const int rowB = tid >> 1;          // 0..127  (TRB B: 4 chunks/thread)
    const int cbB  = (tid & 1) * 4;
    const int br7  = rowB & 7;
    const int krow = tid & 63;          // NN B staging
    const int cg   = tid >> 6;          // 0..3
    const int kr7  = krow & 7;

    // ---- ldmatrix per-lane bases ----
    const int aRow  = wmh * 32 + rl + hk * 8;
    const int bTrow = wnh * 32 + rl + hn * 8;
    int bNN[2];
#pragma unroll
    for (int pair = 0; pair < 2; pair++) {
        int nb   = wnh * 32 + pair * 16 + hn * 8;
        int nh   = nb >> 6;
        int phys = ((nb >> 3) & 7) ^ rl;
        bNN[pair] = 8192 + nh * 8192 + (rl + hk * 8) * 128 + phys * 16;
    }

    float acc[2][4][4];
#pragma unroll
    for (int mt = 0; mt < 2; mt++)
#pragma unroll
        for (int nt = 0; nt < 4; nt++)
#pragma unroll
            for (int i = 0; i < 4; i++) acc[mt][nt][i] = 0.0f;

#define ISSUE(KT, STG) {                                                       \
    unsigned sb = sbase + (STG) * 24576;                                       \
    const __half* asrc = Aop + (size_t)(row0 + rowA) * lda + (KT) * 64 + cbA * 8; \
    _Pragma("unroll")                                                          \
    for (int cc = 0; cc < 2; cc++)                                             \
        CP16(sb + rowA * 128 + (((cbA + cc) ^ ar7) * 16), asrc + cc * 8);      \
    if (BMODE == 1) {                                                          \
        const __half* bsrc = Bop + (size_t)(col0 + rowB) * ldb + (KT) * 64 + cbB * 8; \
        _Pragma("unroll")                                                      \
        for (int cc = 0; cc < 4; cc++)                                         \
            CP16(sb + 8192 + rowB * 128 + (((cbB + cc) ^ br7) * 16), bsrc + cc * 8); \
    } else {                                                                   \
        const __half* bsrc = Bop + (size_t)((KT) * 64 + krow) * ldb + col0;    \
        _Pragma("unroll")                                                      \
        for (int cc = 0; cc < 4; cc++) {                                       \
            int chunk = cg + cc * 4;                                           \
            CP16(sb + 8192 + (chunk >> 3) * 8192 + krow * 128                  \
                    + (((chunk & 7) ^ kr7) * 16), bsrc + chunk * 8);           \
        }                                                                      \
    }                                                                          \
    CP_COMMIT(); }

#define COMPUTE(STG) {                                                         \
    unsigned pb = sbase + (STG) * 24576;                                       \
    _Pragma("unroll")                                                          \
    for (int ksb = 0; ksb < 4; ksb++) {                                        \
        unsigned aF[2][4], bF[4][2];                                           \
        unsigned physA = (unsigned)((2 * ksb + hn) ^ rl);                      \
        unsigned aoff  = pb + aRow * 128 + physA * 16;                         \
        _Pragma("unroll")                                                      \
        for (int mt = 0; mt < 2; mt++)                                         \
            LDSM4(aF[mt][0], aF[mt][1], aF[mt][2], aF[mt][3], aoff + mt * 2048); \
        if (BMODE == 1) {                                                      \
            unsigned physB = (unsigned)((2 * ksb + hk) ^ rl);                  \
            _Pragma("unroll")                                                  \
            for (int pair = 0; pair < 2; pair++) {                             \
                unsigned ba = pb + 8192 + (bTrow + pair * 16) * 128 + physB * 16; \
                LDSM4(bF[pair*2][0], bF[pair*2][1],                            \
                      bF[pair*2+1][0], bF[pair*2+1][1], ba);                   \
            }                                                                  \
        } else {                                                               \
            _Pragma("unroll")                                                  \
            for (int pair = 0; pair < 2; pair++) {                             \
                unsigned ba = pb + bNN[pair] + ksb * 2048;                     \
                LDSM4T(bF[pair*2][0], bF[pair*2][1],                           \
                       bF[pair*2+1][0], bF[pair*2+1][1], ba);                  \
            }                                                                  \
        }                                                                      \
        _Pragma("unroll")                                                      \
        for (int mt = 0; mt < 2; mt++)                                         \
            _Pragma("unroll")                                                  \
            for (int nt = 0; nt < 4; nt++)                                     \
                mma16(acc[mt][nt], aF[mt], bF[nt]);                            \
    } }

    const int ktall = Kdim / 64;
    const int kt0   = TRIL ? (row0 >> 6) : 0;
    const int ktend = TRIL ? min(ktall, (row0 + 64 + BAND) >> 6) : ktall;

    // prologue: up to 2 tiles in flight (empty commits keep group count uniform)
    ISSUE(kt0, 0);
    if (kt0 + 1 < ktend) { ISSUE(kt0 + 1, 1); } else { CP_COMMIT(); }

    for (int kt = kt0; kt < ktend; kt++) {
        CP_WAIT1();                  // all but newest group done -> tile kt ready
        __syncthreads();             // all warps done computing the stage we reuse
        if (kt + 2 < ktend) { ISSUE(kt + 2, (kt + 2 - kt0) % 3); }
        else                { CP_COMMIT(); }
        COMPUTE((kt - kt0) % 3);
    }

    // ======================= epilogues =======================
    if (OMODE == 4) {
        // fused GroupNorm: one group (32 ch) == this warp's n-extent.
        float* Cf = (float*)Cv + (size_t)blockIdx.z * sC;
#pragma unroll
        for (int mt = 0; mt < 2; mt++) {
#pragma unroll
            for (int h = 0; h < 2; h++) {
                float vv[8];
                float s1 = 0.0f;
#pragma unroll
                for (int nt = 0; nt < 4; nt++) {
                    vv[nt * 2]     = acc[mt][nt][2 * h];
                    vv[nt * 2 + 1] = acc[mt][nt][2 * h + 1];
                    s1 += vv[nt * 2] + vv[nt * 2 + 1];
                }
                s1 += __shfl_xor_sync(0xffffffffu, s1, 1);
                s1 += __shfl_xor_sync(0xffffffffu, s1, 2);
                float mu = s1 * (1.0f / 32.0f);
                float s2 = 0.0f;
#pragma unroll
                for (int i = 0; i < 8; i++) {
                    float dv = vv[i] - mu;
                    s2 += dv * dv;
                }
                s2 += __shfl_xor_sync(0xffffffffu, s2, 1);
                s2 += __shfl_xor_sync(0xffffffffu, s2, 2);
                float rs = rsqrtf(s2 * (1.0f / 32.0f) + 1e-6f);
                int r = row0 + wmh * 32 + mt * 16 + g + h * 8;
#pragma unroll
                for (int nt = 0; nt < 4; nt++) {
                    int c = col0 + wnh * 32 + nt * 8 + 2 * q;
                    float o0 = (vv[nt * 2]     - mu) * rs * gwp[c]     + gbp[c];
                    float o1 = (vv[nt * 2 + 1] - mu) * rs * gwp[c + 1] + gbp[c + 1];
                    *(float2*)(Cf + (size_t)r * ldc + c) = make_float2(o0, o1);
                }
            }
        }
    } else {
        __half* Ch = (__half*)Cv + (size_t)blockIdx.z * sC;
        const bool doRope = (OMODE == 2) && (blockIdx.z < 2);
#pragma unroll
        for (int mt = 0; mt < 2; mt++) {
#pragma unroll
            for (int nt = 0; nt < 4; nt++) {
                int r = row0 + wmh * 32 + mt * 16 + g;
                int c = col0 + wnh * 32 + nt * 8 + 2 * q;
                float v0 = acc[mt][nt][0], v1 = acc[mt][nt][1];
                float v2 = acc[mt][nt][2], v3 = acc[mt][nt][3];
                if (OMODE == 1) {
                    int d0 = c - r,       d1 = c + 1 - r;
                    int d2 = c - (r + 8), d3 = c + 1 - (r + 8);
                    v0 = (d0 >= 0) ? v0 * g_decay[d0] : 0.0f;
                    v1 = (d1 >= 0) ? v1 * g_decay[d1] : 0.0f;
                    v2 = (d2 >= 0) ? v2 * g_decay[d2] : 0.0f;
                    v3 = (d3 >= 0) ? v3 * g_decay[d3] : 0.0f;
                } else {
                    if (doRope && c < 64) {
                        int cp = c >> 1;
                        float2 cs0 = g_rope[((r)     & (SEQ - 1)) * 32 + cp];
                        float2 cs1 = g_rope[((r + 8) & (SEQ - 1)) * 32 + cp];
                        float a0 = v0, b0 = v1, a1 = v2, b1 = v3;
                        v0 = a0 * cs0.x - b0 * cs0.y;
                        v1 = b0 * cs0.x + a0 * cs0.y;
                        v2 = a1 * cs1.x - b1 * cs1.y;
                        v3 = b1 * cs1.x + a1 * cs1.y;
                    }
                    v0 = silu(v0); v1 = silu(v1);
                    v2 = silu(v2); v3 = silu(v3);
                }
                *(__half2*)(Ch + (size_t)r * ldc + c)       = __floats2half2_rn(v0, v1);
                *(__half2*)(Ch + (size_t)(r + 8) * ldc + c) = __floats2half2_rn(v2, v3);
            }
        }
    }
#undef ISSUE
#undef COMPUTE
}

// ---------------------------------------------------------------------------
#define SMEM_BYTES (3 * 24576)

extern "C" void kernel_launch(void* const* d_in, const int* in_sizes, int n_in,
                              void* d_out, int out_size)
{
    (void)in_sizes; (void)n_in; (void)out_size;
    const float* X  = (const float*)d_in[0];
    const float* WQ = (const float*)d_in[1];
    const float* WK = (const float*)d_in[2];
    const float* WV = (const float*)d_in[3];
    const float* gw = (const float*)d_in[4];
    const float* gb = (const float*)d_in[5];
    float* out = (float*)d_out;

    __half *pXh, *pWh, *pQKV, *pAh;
    cudaGetSymbolAddress((void**)&pXh,  g_Xh);
    cudaGetSymbolAddress((void**)&pWh,  g_Wh);
    cudaGetSymbolAddress((void**)&pQKV, g_QKV);
    cudaGetSymbolAddress((void**)&pAh,  g_Ah);

    cudaFuncSetAttribute(hgemm<0,2,false>, cudaFuncAttributeMaxDynamicSharedMemorySize, SMEM_BYTES);
    cudaFuncSetAttribute(hgemm<1,1,false>, cudaFuncAttributeMaxDynamicSharedMemorySize, SMEM_BYTES);
    cudaFuncSetAttribute(hgemm<0,4,true >, cudaFuncAttributeMaxDynamicSharedMemorySize, SMEM_BYTES);

    init_tables_kernel<<<(SEQ * 32 + 255) / 256, 256>>>();

    // fp32 -> fp16 operand conversion
    int nx = BATCH * SEQ * DMODEL, nw = DMODEL * DMODEL;
    cvt_kernel<<<(nx + 255) / 256, 256>>>(X, pXh, nx);
    cvt_w_kernel<<<(3 * nw + 255) / 256, 256>>>(WQ, WK, WV, pWh);

    // All three projections in ONE launch: z=0(Q,rope) 1(K,rope) 2(V)
    size_t nqkv = (size_t)BATCH * SEQ * DMODEL;
    dim3 gProj(DMODEL / 128, (BATCH * SEQ) / 64, 3);
    hgemm<0,2,false><<<gProj, 256, SMEM_BYTES>>>(pXh, pWh, pQKV, 0, 0,
                                                 DMODEL, DMODEL, DMODEL, DMODEL,
                                                 0, (size_t)nw, nqkv);

    // A = Q K^T (TRB) with decay epilogue -> fp16; banded tiles only
    dim3 gA(SEQ / 128, SEQ / 64, BATCH);
    hgemm<1,1,false><<<gA, 256, SMEM_BYTES>>>(pQKV + 0 * nqkv, pQKV + 1 * nqkv, pAh, 0, 0,
                                              DMODEL, DMODEL, DMODEL, SEQ,
                                              (size_t)SEQ * DMODEL, (size_t)SEQ * DMODEL,
                                              (size_t)SEQ * SEQ);

    // O = A V (NN, banded TRIL) with fused GroupNorm -> d_out (fp32)
    dim3 gO(DMODEL / 128, SEQ / 64, BATCH);
    hgemm<0,4,true><<<gO, 256, SMEM_BYTES>>>(pAh, pQKV + 2 * nqkv, out, gw, gb,
                                             SEQ, SEQ, DMODEL, DMODEL,
                                             (size_t)SEQ * SEQ, (size_t)SEQ * DMODEL,
                                             (size_t)SEQ * DMODEL);
}

// round 17
// speedup vs baseline: 1.1111x; 1.1111x over previous
#include <cuda_runtime.h>
#include <cuda_fp16.h>
#include <math.h>

#define BATCH 2
#define SEQ   4096
#define DMODEL 1024
#define BAND  2048   // decay band: gamma^2048 = e^-10.2; tail ~1.7e-4 in quadrature

// Scratch (alloc-free rule: __device__ globals)
__device__ __half g_Xh[BATCH * SEQ * DMODEL];
__device__ __half g_Wh[3][DMODEL * DMODEL];
__device__ __half g_QKV[3][BATCH * SEQ * DMODEL];    // Q, K, V (fp16, post-act)
__device__ __half g_Ah[(size_t)BATCH * SEQ * SEQ];   // 67 MB; out-of-band never read
__device__ float  g_decay[SEQ];
__device__ float2 g_rope[SEQ * 32];

// ---------------------------------------------------------------------------
// One fused prep kernel: rope/decay tables + X->fp16 + W{Q,K,V}->fp16.
// Grid-stride over the concatenated index space.
// ---------------------------------------------------------------------------
#define N_TBL (SEQ * 32)
#define N_X   (BATCH * SEQ * DMODEL)
#define N_W   (DMODEL * DMODEL)

__global__ void prep_kernel(const float* __restrict__ X,
                            const float* __restrict__ w0,
                            const float* __restrict__ w1,
                            const float* __restrict__ w2)
{
    int total = N_TBL + N_X + 3 * N_W;
    for (int i = blockIdx.x * blockDim.x + threadIdx.x; i < total;
         i += gridDim.x * blockDim.x) {
        if (i < N_TBL) {
            int t = i >> 5, cp = i & 31;
            double fr = (double)t * exp((double)cp * -0.28782313662425574);
            g_rope[i] = make_float2((float)cos(fr), (float)sin(fr));
            if (cp == 0) g_decay[t] = (float)exp((double)t * log(255.0 / 256.0));
        } else if (i < N_TBL + N_X) {
            int j = i - N_TBL;
            g_Xh[j] = __float2half(X[j]);
        } else {
            int j = i - N_TBL - N_X;
            int s = j / N_W, k = j - s * N_W;
            const float* w = (s == 0) ? w0 : (s == 1) ? w1 : w2;
            g_Wh[0][j] = __float2half(w[k]);
        }
    }
}

__device__ __forceinline__ unsigned smem_u32(const void* p) {
    return (unsigned)__cvta_generic_to_shared(p);
}
#define CP16(dst, src) \
    asm volatile("cp.async.cg.shared.global [%0], [%1], 16;" :: "r"(dst), "l"(src))
#define CP_COMMIT()  asm volatile("cp.async.commit_group;")
#define CP_WAIT1()   asm volatile("cp.async.wait_group 1;")

#define LDSM4(R0, R1, R2, R3, ADDR) \
    asm volatile("ldmatrix.sync.aligned.m8n8.x4.shared.b16 {%0,%1,%2,%3}, [%4];" \
                 : "=r"(R0), "=r"(R1), "=r"(R2), "=r"(R3) : "r"(ADDR))
#define LDSM4T(R0, R1, R2, R3, ADDR) \
    asm volatile("ldmatrix.sync.aligned.m8n8.x4.trans.shared.b16 {%0,%1,%2,%3}, [%4];" \
                 : "=r"(R0), "=r"(R1), "=r"(R2), "=r"(R3) : "r"(ADDR))

__device__ __forceinline__ void mma16(float* c, const unsigned* a, const unsigned* b) {
    asm volatile(
        "mma.sync.aligned.m16n8k16.row.col.f32.f16.f16.f32 "
        "{%0,%1,%2,%3}, {%4,%5,%6,%7}, {%8,%9}, {%0,%1,%2,%3};"
        : "+f"(c[0]), "+f"(c[1]), "+f"(c[2]), "+f"(c[3])
        : "r"(a[0]), "r"(a[1]), "r"(a[2]), "r"(a[3]), "r"(b[0]), "r"(b[1]));
}
__device__ __forceinline__ float silu(float x) { return x / (1.0f + expf(-x)); }

// ---------------------------------------------------------------------------
// fp16 tensor-core GEMM, cp.async + ldmatrix + XOR swizzle.
// Block 128x128, K-tile 64, 256 threads, 8 warps (2x4), warp tile 64x32.
// 3 smem stages x 32KB, cp.async depth-2 prefetch via wait_group 1.
//
// Smem per 32KB stage: A tile [row][128B of k], chunk c at phys = c ^ (row&7).
// B at +16384:  BMODE==1 (TRB, NxK): same layout (row=n).
//               BMODE==0 (NN, KxN): 2 subtiles [nh][krow][128B of n],
//               consumed via ldmatrix.trans.
// OMODE: 1 fp16 out + anti-causal decay; COMPACT banded grid:
//          col0 = row0 + 128*blockIdx.x (blockIdx.x in [0,17)), clip col0>=SEQ.
//          Exactly the tiles with 0 <= col0-row0 <= BAND.
//        2 fp16 out + silu, rope iff blockIdx.z < 2 (fused QKV projection;
//          z selects weight via sB and output slice via sC)
//        4 fp32 out + fused GroupNorm (AV epilogue; group == warp n-extent)
// TRIL:  A operand banded upper-triangular -> K loop runs
//        [row0/64, (row0+128+BAND)/64) — exactly the written A columns.
// ---------------------------------------------------------------------------
template<int BMODE, int OMODE, bool TRIL>
__global__ void __launch_bounds__(256, 2) hgemm(
    const __half* __restrict__ Ag, const __half* __restrict__ Bg,
    void* __restrict__ Cv,
    const float* __restrict__ gwp, const float* __restrict__ gbp,
    int Kdim, int lda, int ldb, int ldc,
    size_t sA, size_t sB, size_t sC)
{
    extern __shared__ __half S[];

    const int row0 = blockIdx.y * 128;
    const int col0 = (OMODE == 1) ? row0 + blockIdx.x * 128 : blockIdx.x * 128;
    if (OMODE == 1 && col0 >= SEQ) return;   // band clipped at sequence edge

    const __half* Aop = Ag + (size_t)blockIdx.z * sA;
    const __half* Bop = Bg + (size_t)blockIdx.z * sB;

    const int tid  = threadIdx.x;
    const int lane = tid & 31;
    const int wid  = tid >> 5;
    const int wmh  = wid & 1;           // warp m-half -> m off 64
    const int wnh  = wid >> 1;          // warp n-quarter -> n off 32
    const int g    = lane >> 2;
    const int q    = lane & 3;
    const int rl   = lane & 7;
    const int hk   = (lane >> 3) & 1;
    const int hn   = (lane >> 4) & 1;

    const unsigned sbase = smem_u32(S);

    // ---- cp.async staging indices ----
    const int rowA = tid >> 1;          // 0..127
    const int cb   = (tid & 1) * 4;     // chunk base 0/4
    const int ar7  = rowA & 7;
    const int krow = tid & 63;          // NN B staging
    const int cg   = tid >> 6;          // 0..3
    const int kr7  = krow & 7;

    // ---- ldmatrix per-lane bases ----
    const int aRow  = wmh * 64 + rl + hk * 8;
    const int bTrow = wnh * 32 + rl + hn * 8;
    int bNN[2];
#pragma unroll
    for (int pair = 0; pair < 2; pair++) {
        int nb   = wnh * 32 + pair * 16 + hn * 8;
        int nh   = nb >> 6;
        int phys = ((nb >> 3) & 7) ^ rl;
        bNN[pair] = 16384 + nh * 8192 + (rl + hk * 8) * 128 + phys * 16;
    }

    float acc[4][4][4];
#pragma unroll
    for (int mt = 0; mt < 4; mt++)
#pragma unroll
        for (int nt = 0; nt < 4; nt++)
#pragma unroll
            for (int i = 0; i < 4; i++) acc[mt][nt][i] = 0.0f;

#define ISSUE(KT, STG) {                                                       \
    unsigned sb = sbase + (STG) * 32768;                                       \
    const __half* asrc = Aop + (size_t)(row0 + rowA) * lda + (KT) * 64 + cb * 8; \
    _Pragma("unroll")                                                          \
    for (int cc = 0; cc < 4; cc++)                                             \
        CP16(sb + rowA * 128 + (((cb + cc) ^ ar7) * 16), asrc + cc * 8);       \
    if (BMODE == 1) {                                                          \
        const __half* bsrc = Bop + (size_t)(col0 + rowA) * ldb + (KT) * 64 + cb * 8; \
        _Pragma("unroll")                                                      \
        for (int cc = 0; cc < 4; cc++)                                         \
            CP16(sb + 16384 + rowA * 128 + (((cb + cc) ^ ar7) * 16), bsrc + cc * 8); \
    } else {                                                                   \
        const __half* bsrc = Bop + (size_t)((KT) * 64 + krow) * ldb + col0;    \
        _Pragma("unroll")                                                      \
        for (int cc = 0; cc < 4; cc++) {                                       \
            int chunk = cg + cc * 4;                                           \
            CP16(sb + 16384 + (chunk >> 3) * 8192 + krow * 128                 \
                    + (((chunk & 7) ^ kr7) * 16), bsrc + chunk * 8);           \
        }                                                                      \
    }                                                                          \
    CP_COMMIT(); }

#define COMPUTE(STG) {                                                         \
    unsigned pb = sbase + (STG) * 32768;                                       \
    _Pragma("unroll")                                                          \
    for (int ksb = 0; ksb < 4; ksb++) {                                        \
        unsigned aF[4][4], bF[4][2];                                           \
        unsigned physA = (unsigned)((2 * ksb + hn) ^ rl);                      \
        unsigned aoff  = pb + aRow * 128 + physA * 16;                         \
        _Pragma("unroll")                                                      \
        for (int mt = 0; mt < 4; mt++)                                         \
            LDSM4(aF[mt][0], aF[mt][1], aF[mt][2], aF[mt][3], aoff + mt * 2048); \
        if (BMODE == 1) {                                                      \
            unsigned physB = (unsigned)((2 * ksb + hk) ^ rl);                  \
            _Pragma("unroll")                                                  \
            for (int pair = 0; pair < 2; pair++) {                             \
                unsigned ba = pb + 16384 + (bTrow + pair * 16) * 128 + physB * 16; \
                LDSM4(bF[pair*2][0], bF[pair*2][1],                            \
                      bF[pair*2+1][0], bF[pair*2+1][1], ba);                   \
            }                                                                  \
        } else {                                                               \
            _Pragma("unroll")                                                  \
            for (int pair = 0; pair < 2; pair++) {                             \
                unsigned ba = pb + bNN[pair] + ksb * 2048;                     \
                LDSM4T(bF[pair*2][0], bF[pair*2][1],                           \
                       bF[pair*2+1][0], bF[pair*2+1][1], ba);                  \
            }                                                                  \
        }                                                                      \
        _Pragma("unroll")                                                      \
        for (int mt = 0; mt < 4; mt++)                                         \
            _Pragma("unroll")                                                  \
            for (int nt = 0; nt < 4; nt++)                                     \
                mma16(acc[mt][nt], aF[mt], bF[nt]);                            \
    } }

    const int ktall = Kdim / 64;
    const int kt0   = TRIL ? (row0 >> 6) : 0;
    const int ktend = TRIL ? min(ktall, (row0 + 128 + BAND) >> 6) : ktall;

    // prologue: up to 2 tiles in flight (empty commits keep group count uniform)
    ISSUE(kt0, 0);
    if (kt0 + 1 < ktend) { ISSUE(kt0 + 1, 1); } else { CP_COMMIT(); }

    for (int kt = kt0; kt < ktend; kt++) {
        CP_WAIT1();                  // all but newest group done -> tile kt ready
        __syncthreads();             // all warps done computing the stage we reuse
        if (kt + 2 < ktend) { ISSUE(kt + 2, (kt + 2 - kt0) % 3); }
        else                { CP_COMMIT(); }
        COMPUTE((kt - kt0) % 3);
    }

    // ======================= epilogues =======================
    if (OMODE == 4) {
        // fused GroupNorm: one group (32 ch) == this warp's n-extent.
        float* Cf = (float*)Cv + (size_t)blockIdx.z * sC;
#pragma unroll
        for (int mt = 0; mt < 4; mt++) {
#pragma unroll
            for (int h = 0; h < 2; h++) {
                float vv[8];
                float s1 = 0.0f;
#pragma unroll
                for (int nt = 0; nt < 4; nt++) {
                    vv[nt * 2]     = acc[mt][nt][2 * h];
                    vv[nt * 2 + 1] = acc[mt][nt][2 * h + 1];
                    s1 += vv[nt * 2] + vv[nt * 2 + 1];
                }
                s1 += __shfl_xor_sync(0xffffffffu, s1, 1);
                s1 += __shfl_xor_sync(0xffffffffu, s1, 2);
                float mu = s1 * (1.0f / 32.0f);
                float s2 = 0.0f;
#pragma unroll
                for (int i = 0; i < 8; i++) {
                    float dv = vv[i] - mu;
                    s2 += dv * dv;
                }
                s2 += __shfl_xor_sync(0xffffffffu, s2, 1);
                s2 += __shfl_xor_sync(0xffffffffu, s2, 2);
                float rs = rsqrtf(s2 * (1.0f / 32.0f) + 1e-6f);
                int r = row0 + wmh * 64 + mt * 16 + g + h * 8;
#pragma unroll
                for (int nt = 0; nt < 4; nt++) {
                    int c = col0 + wnh * 32 + nt * 8 + 2 * q;
                    float o0 = (vv[nt * 2]     - mu) * rs * gwp[c]     + gbp[c];
                    float o1 = (vv[nt * 2 + 1] - mu) * rs * gwp[c + 1] + gbp[c + 1];
                    *(float2*)(Cf + (size_t)r * ldc + c) = make_float2(o0, o1);
                }
            }
        }
    } else {
        __half* Ch = (__half*)Cv + (size_t)blockIdx.z * sC;
        const bool doRope = (OMODE == 2) && (blockIdx.z < 2);
#pragma unroll
        for (int mt = 0; mt < 4; mt++) {
#pragma unroll
            for (int nt = 0; nt < 4; nt++) {
                int r = row0 + wmh * 64 + mt * 16 + g;
                int c = col0 + wnh * 32 + nt * 8 + 2 * q;
                float v0 = acc[mt][nt][0], v1 = acc[mt][nt][1];
                float v2 = acc[mt][nt][2], v3 = acc[mt][nt][3];
                if (OMODE == 1) {
                    int d0 = c - r,       d1 = c + 1 - r;
                    int d2 = c - (r + 8), d3 = c + 1 - (r + 8);
                    v0 = (d0 >= 0) ? v0 * g_decay[d0] : 0.0f;
                    v1 = (d1 >= 0) ? v1 * g_decay[d1] : 0.0f;
                    v2 = (d2 >= 0) ? v2 * g_decay[d2] : 0.0f;
                    v3 = (d3 >= 0) ? v3 * g_decay[d3] : 0.0f;
                } else {
                    if (doRope && c < 64) {
                        int cp = c >> 1;
                        float2 cs0 = g_rope[((r)     & (SEQ - 1)) * 32 + cp];
                        float2 cs1 = g_rope[((r + 8) & (SEQ - 1)) * 32 + cp];
                        float a0 = v0, b0 = v1, a1 = v2, b1 = v3;
                        v0 = a0 * cs0.x - b0 * cs0.y;
                        v1 = b0 * cs0.x + a0 * cs0.y;
                        v2 = a1 * cs1.x - b1 * cs1.y;
                        v3 = b1 * cs1.x + a1 * cs1.y;
                    }
                    v0 = silu(v0); v1 = silu(v1);
                    v2 = silu(v2); v3 = silu(v3);
                }
                *(__half2*)(Ch + (size_t)r * ldc + c)       = __floats2half2_rn(v0, v1);
                *(__half2*)(Ch + (size_t)(r + 8) * ldc + c) = __floats2half2_rn(v2, v3);
            }
        }
    }
#undef ISSUE
#undef COMPUTE
}

// ---------------------------------------------------------------------------
#define SMEM_BYTES (3 * 32768)

extern "C" void kernel_launch(void* const* d_in, const int* in_sizes, int n_in,
                              void* d_out, int out_size)
{
    (void)in_sizes; (void)n_in; (void)out_size;
    const float* X  = (const float*)d_in[0];
    const float* WQ = (const float*)d_in[1];
    const float* WK = (const float*)d_in[2];
    const float* WV = (const float*)d_in[3];
    const float* gw = (const float*)d_in[4];
    const float* gb = (const float*)d_in[5];
    float* out = (float*)d_out;

    __half *pXh, *pWh, *pQKV, *pAh;
    cudaGetSymbolAddress((void**)&pXh,  g_Xh);
    cudaGetSymbolAddress((void**)&pWh,  g_Wh);
    cudaGetSymbolAddress((void**)&pQKV, g_QKV);
    cudaGetSymbolAddress((void**)&pAh,  g_Ah);

    cudaFuncSetAttribute(hgemm<0,2,false>, cudaFuncAttributeMaxDynamicSharedMemorySize, SMEM_BYTES);
    cudaFuncSetAttribute(hgemm<1,1,false>, cudaFuncAttributeMaxDynamicSharedMemorySize, SMEM_BYTES);
    cudaFuncSetAttribute(hgemm<0,4,true >, cudaFuncAttributeMaxDynamicSharedMemorySize, SMEM_BYTES);

    // Fused prep: tables + all fp32->fp16 conversions in one launch
    prep_kernel<<<1184, 256>>>(X, WQ, WK, WV);

    // All three projections in ONE launch: z=0(Q,rope) 1(K,rope) 2(V)
    int nw = DMODEL * DMODEL;
    size_t nqkv = (size_t)BATCH * SEQ * DMODEL;
    dim3 gProj(DMODEL / 128, (BATCH * SEQ) / 128, 3);
    hgemm<0,2,false><<<gProj, 256, SMEM_BYTES>>>(pXh, pWh, pQKV, 0, 0,
                                                 DMODEL, DMODEL, DMODEL, DMODEL,
                                                 0, (size_t)nw, nqkv);

    // A = Q K^T (TRB) with decay epilogue -> fp16; COMPACT banded grid
    // (17 diagonals x 32 row-tiles x 2 batches; col0 = row0 + 128*x)
    dim3 gA(BAND / 128 + 1, SEQ / 128, BATCH);
    hgemm<1,1,false><<<gA, 256, SMEM_BYTES>>>(pQKV + 0 * nqkv, pQKV + 1 * nqkv, pAh, 0, 0,
                                              DMODEL, DMODEL, DMODEL, SEQ,
                                              (size_t)SEQ * DMODEL, (size_t)SEQ * DMODEL,
                                              (size_t)SEQ * SEQ);

    // O = A V (NN, banded TRIL) with fused GroupNorm -> d_out (fp32)
    dim3 gO(DMODEL / 128, SEQ / 128, BATCH);
    hgemm<0,4,true><<<gO, 256, SMEM_BYTES>>>(pAh, pQKV + 2 * nqkv, out, gw, gb,
                                             SEQ, SEQ, DMODEL, DMODEL,
                                             (size_t)SEQ * SEQ, (size_t)SEQ * DMODEL,
                                             (size_t)SEQ * DMODEL);
}